// round 17
// baseline (speedup 1.0000x reference)
#include <cuda_runtime.h>
#include <cuda_fp16.h>
#include <math.h>

// Caps1D dynamic routing — round 17.
// R16 + half2 value-splitting reduction butterfly:
//  * cross-lane S[16] reduction runs fully in half2: 3 splitting stages
//    (8->4->2->1 words) + 2 plain HADD2 stages = 9 shfl + 9 HADD2
//    (was 24 shfl + 24 FADD in fp32), no sh->s[16] unpack.
//  * warp partials stored as half2 (8 STS.32/warp); cross-warp stage in
//    fp32 (t<8, one component-pair per thread) to keep large-magnitude
//    accumulation accurate. Z (softmax denom) butterfly stays fp32.
// Everything else from R16: grid 2048, 2 CTAs/SM, register u_ji (40 half2),
// HFMA2 phase 1 from prologue-packed fp16 W, fused dot->exp->half2-S sweeps,
// final reduction short-circuited to a single barrier + direct out[] write.

namespace {
constexpr int T    = 512;
constexpr int Rdim = 2336;
constexpr int Kdim = 2;
constexpr int Bdim = 1024;
constexpr int NW   = T / 32;
constexpr int J    = 5;                    // rows per thread
constexpr int WCONV = Kdim * J * 8 * 512;  // int4 elements in packed W
}

// Packed fp16 W: [k][j][c][t] -> int4. c = 2*m + hc; int4 holds 4 half2
// covering p = hc*8 .. hc*8+7 for that m. Rows >= Rdim are zero.
__device__ int4 W2dev[WCONV];

__global__ void convert_w_kernel(const float* __restrict__ W) {
    const int idx = blockIdx.x * blockDim.x + threadIdx.x;
    if (idx >= WCONV) return;
    const int t  = idx & 511;
    const int c  = (idx >> 9) & 7;
    const int kj = idx >> 12;
    const int j  = kj % J;
    const int k  = kj / J;
    const int row = j * 512 + t;
    const int m   = c >> 1;
    const int hc  = c & 1;
    int4 o = make_int4(0, 0, 0, 0);
    if (row < Rdim) {
        const float4* src = reinterpret_cast<const float4*>(W)
                          + ((size_t)(k * Rdim + row) * 4 + m) * 4 + hc * 2;
        float4 a = src[0];
        float4 b = src[1];
        __half2 h0 = __floats2half2_rn(a.x, a.y);
        __half2 h1 = __floats2half2_rn(a.z, a.w);
        __half2 h2 = __floats2half2_rn(b.x, b.y);
        __half2 h3 = __floats2half2_rn(b.z, b.w);
        o.x = *reinterpret_cast<int*>(&h0);
        o.y = *reinterpret_cast<int*>(&h1);
        o.z = *reinterpret_cast<int*>(&h2);
        o.w = *reinterpret_cast<int*>(&h3);
    }
    W2dev[idx] = o;
}

__device__ __forceinline__ __half2 shflxor_h2(__half2 v, int m) {
    unsigned u = *reinterpret_cast<unsigned*>(&v);
    unsigned r = __shfl_xor_sync(0xffffffffu, u, m);
    return *reinterpret_cast<__half2*>(&r);
}

// Dual-accumulator fp16 dot: <h[0..7], vh[0..7]> (16 scalar products).
__device__ __forceinline__ float dot16h(const __half2* hj, const __half2* vh) {
    __half2 a = __hmul2(hj[0], vh[0]);
    __half2 b = __hmul2(hj[1], vh[1]);
    a = __hfma2(hj[2], vh[2], a);  b = __hfma2(hj[3], vh[3], b);
    a = __hfma2(hj[4], vh[4], a);  b = __hfma2(hj[5], vh[5], b);
    a = __hfma2(hj[6], vh[6], a);  b = __hfma2(hj[7], vh[7], b);
    float2 fa = __half22float2(a);
    float2 fb = __half22float2(b);
    return (fa.x + fa.y) + (fb.x + fb.y);
}

__global__ __launch_bounds__(T, 2)
void caps_routing_kernel(const float* __restrict__ u,
                         float* __restrict__ out) {
    // Double-buffered reduction scratch.
    __shared__ __half2 redH[2][NW * 8];     // warp partial pairs (half2)
    __shared__ float   redW[2][NW];         // warp lsum partials
    __shared__ __half2 vbufh[2][8];         // published v (half2 pairs)

    const int t    = threadIdx.x;
    const int lane = t & 31;
    const int wid  = t >> 5;
    const int bid  = blockIdx.x;
    const int b    = bid >> 1;
    const int k    = bid & 1;
    const unsigned F = 0xffffffffu;

    const float4* U4 = reinterpret_cast<const float4*>(u) + (size_t)b * Rdim;

    // ---------------- Phase 1: u_ji -> fp16 registers (HFMA2) ----------------
    __half2 h[J][8];   // h[j][pp] = (p=2pp, p=2pp+1)

    #pragma unroll
    for (int j = 0; j < J; j++) {
        const int row  = j * 512 + t;
        const int rowc = row < Rdim ? row : Rdim - 1;   // clamp; W=0 masks tail
        float4 u4 = U4[rowc];
        __half2 u0 = __float2half2_rn(u4.x);
        __half2 u1 = __float2half2_rn(u4.y);
        __half2 u2 = __float2half2_rn(u4.z);
        __half2 u3 = __float2half2_rn(u4.w);

        const int4* Wp = W2dev + (size_t)(k * J + j) * 8 * 512 + t;
        int4 wa[8];
        #pragma unroll
        for (int c = 0; c < 8; c++) wa[c] = Wp[c * 512];   // 8 coalesced LDG.128
        const __half2* wh = reinterpret_cast<const __half2*>(wa);

        #pragma unroll
        for (int hc = 0; hc < 2; hc++) {
            #pragma unroll
            for (int i = 0; i < 4; i++) {
                __half2 acc = __hmul2(u3, wh[(6 + hc) * 4 + i]);
                acc = __hfma2(u2, wh[(4 + hc) * 4 + i], acc);
                acc = __hfma2(u1, wh[(2 + hc) * 4 + i], acc);
                acc = __hfma2(u0, wh[(0 + hc) * 4 + i], acc);
                h[j][hc * 4 + i] = acc;
            }
        }
    }

    // ---------------- Phase 2: routing (lane-local rows) ----------------
    float d[J];
    #pragma unroll
    for (int j = 0; j < J; j++) d[j] = (j * 512 + t < Rdim) ? 0.f : -1.0e30f;

    __half2 vh[8];

    // Half2 value-splitting butterfly over sh[8] (16 comps); optional fp32
    // lsum butterfly. Writes warp partials to redH/redW[buf].
    auto butterflyStoreH = [&](const __half2* sh, float lsum, bool use_z, int buf) {
        __half2 a4[4];
        {
            const bool hi = (lane & 16) != 0;
            #pragma unroll
            for (int i = 0; i < 4; i++) {
                __half2 send = hi ? sh[i] : sh[4 + i];
                __half2 keep = hi ? sh[4 + i] : sh[i];
                a4[i] = __hadd2(keep, shflxor_h2(send, 16));
            }
        }
        __half2 b2[2];
        {
            const bool hi = (lane & 8) != 0;
            #pragma unroll
            for (int i = 0; i < 2; i++) {
                __half2 send = hi ? a4[i] : a4[2 + i];
                __half2 keep = hi ? a4[2 + i] : a4[i];
                b2[i] = __hadd2(keep, shflxor_h2(send, 8));
            }
        }
        __half2 c1;
        {
            const bool hi = (lane & 4) != 0;
            __half2 send = hi ? b2[0] : b2[1];
            __half2 keep = hi ? b2[1] : b2[0];
            c1 = __hadd2(keep, shflxor_h2(send, 4));
        }
        c1 = __hadd2(c1, shflxor_h2(c1, 2));
        c1 = __hadd2(c1, shflxor_h2(c1, 1));
        if (use_z) {
            #pragma unroll
            for (int o = 16; o >= 1; o >>= 1) lsum += __shfl_xor_sync(F, lsum, o);
        }
        if ((lane & 3) == 0) redH[buf][wid * 8 + (lane >> 2)] = c1;  // pair idx
        if (use_z && lane == 0) redW[buf][wid] = lsum;
    };

    // Full reduction with v publication: 2 barriers. Stage 2 on t<8 (fp32).
    auto reduceV = [&](const __half2* sh, float lsum, bool use_z,
                       float fixed_pre, int buf) {
        butterflyStoreH(sh, lsum, use_z, buf);
        __syncthreads();
        if (t < 8) {   // warp 0 lanes 0..7: component pair t
            float ax = 0.f, ay = 0.f;
            #pragma unroll
            for (int w = 0; w < NW; ++w) {
                float2 f = __half22float2(redH[buf][w * 8 + t]);
                ax += f.x; ay += f.y;
            }
            float pre = fixed_pre;
            if (use_z) {
                float Z = 0.f;
                #pragma unroll
                for (int w = 0; w < NW; ++w) Z += redW[buf][w];
                pre = __frcp_rn(Z);
            }
            ax *= pre; ay *= pre;
            float nn = ax * ax + ay * ay;
            #pragma unroll
            for (int o = 4; o >= 1; o >>= 1) nn += __shfl_xor_sync(0x000000ffu, nn, o);
            float vf = sqrtf(nn) / (1.f + nn);
            vbufh[buf][t] = __floats2half2_rn(ax * vf, ay * vf);
        }
        __syncthreads();
    };

    // ---- sweep 0: uniform-c sum (pure half2) ----
    {
        __half2 sh[8];
        #pragma unroll
        for (int pp = 0; pp < 8; pp++) {
            __half2 acc = h[0][pp];
            #pragma unroll
            for (int j = 1; j < J; j++) acc = __hadd2(acc, h[j][pp]);  // tail rows 0
            sh[pp] = acc;
        }
        reduceV(sh, 0.f, false, 1.0f / (float)Rdim, 0);
        #pragma unroll
        for (int pp = 0; pp < 8; pp++) vh[pp] = vbufh[0][pp];
    }

    // ---- fused sweep 1: dot -> exp -> half2 exp-weighted S (needs v) ----
    {
        __half2 sh[8];
        #pragma unroll
        for (int pp = 0; pp < 8; pp++) sh[pp] = __half2half2(__float2half_rn(0.f));
        float lsum = 0.f;
        #pragma unroll
        for (int j = 0; j < J; j++) {
            float dd = dot16h(h[j], vh);          // tail rows: h=0 -> dd=0
            float dn = d[j] + dd;                 // invalid rows stay -1e30
            d[j] = dn;
            float e = __expf(dn);                 // invalid -> 0; e ~ O(1)
            lsum += e;
            __half2 eh = __half2half2(__float2half_rn(e));
            #pragma unroll
            for (int pp = 0; pp < 8; pp++) sh[pp] = __hfma2(eh, h[j][pp], sh[pp]);
        }
        reduceV(sh, lsum, true, 0.f, 1);
        #pragma unroll
        for (int pp = 0; pp < 8; pp++) vh[pp] = vbufh[1][pp];
    }

    // ---- fused sweep 2 (final): dot -> exp -> S; only norm needed ----
    {
        __half2 sh[8];
        #pragma unroll
        for (int pp = 0; pp < 8; pp++) sh[pp] = __half2half2(__float2half_rn(0.f));
        float lsum = 0.f;
        #pragma unroll
        for (int j = 0; j < J; j++) {
            float dd = dot16h(h[j], vh);
            float e = __expf(d[j] + dd);          // invalid -> 0
            lsum += e;
            __half2 eh = __half2half2(__float2half_rn(e));
            #pragma unroll
            for (int pp = 0; pp < 8; pp++) sh[pp] = __hfma2(eh, h[j][pp], sh[pp]);
        }
        butterflyStoreH(sh, lsum, true, 0);
        __syncthreads();                           // single barrier
        if (t < 8) {                               // warp 0 finishes and writes
            float ax = 0.f, ay = 0.f;
            #pragma unroll
            for (int w = 0; w < NW; ++w) {
                float2 f = __half22float2(redH[0][w * 8 + t]);
                ax += f.x; ay += f.y;
            }
            float Z = 0.f;
            #pragma unroll
            for (int w = 0; w < NW; ++w) Z += redW[0][w];
            float pre = __frcp_rn(Z);
            ax *= pre; ay *= pre;
            float nn = ax * ax + ay * ay;
            #pragma unroll
            for (int o = 4; o >= 1; o >>= 1) nn += __shfl_xor_sync(0x000000ffu, nn, o);
            if (t == 0) out[bid] = nn / (1.f + nn);
        }
    }
}

extern "C" void kernel_launch(void* const* d_in, const int* in_sizes, int n_in,
                              void* d_out, int out_size) {
    const float* u = (const float*)d_in[0];   // [B, R, M] fp32
    const float* W = (const float*)d_in[1];   // [K, R, M, P] fp32
    float* out = (float*)d_out;               // [B, K] fp32

    convert_w_kernel<<<(WCONV + 255) / 256, 256>>>(W);
    caps_routing_kernel<<<Bdim * Kdim, T>>>(u, out);
}